// round 1
// baseline (speedup 1.0000x reference)
#include <cuda_runtime.h>

#define BB 8
#define TT 1024
#define DD 1024
#define FF 4096
#define MM (BB*TT)          // 8192 rows
#define D4 (DD/4)

// ---------------- scratch (static device allocations; allowed) ----------------
__device__ float g_xn [MM*DD];
__device__ float g_mk [MM*DD];
__device__ float g_mv [MM*DD];
__device__ float g_mr [MM*DD];
__device__ float g_k  [MM*DD];
__device__ float g_v  [MM*DD];
__device__ float g_r  [MM*DD];
__device__ float g_rw [MM*DD];   // r * wkv
__device__ float g_x1 [MM*DD];
__device__ float g_xn2[MM*DD];
__device__ float g_mck[MM*DD];
__device__ float g_mcr[MM*DD];
__device__ float g_kc [MM*FF];   // relu(.)^2 of channel-mix key
__device__ float g_rc [MM*DD];

// ---------------- LayerNorm: one block per row, D=1024, 256 threads ----------------
__global__ void __launch_bounds__(256) ln_kernel(
    const float* __restrict__ x, const float* __restrict__ g,
    const float* __restrict__ b, float* __restrict__ y,
    float* __restrict__ last)   // last: [B,D] slot for t==T-1 rows (may be null)
{
    const int row = blockIdx.x;                 // 0..MM-1
    const float4* xr = (const float4*)(x + (size_t)row * DD);
    float4 v = xr[threadIdx.x];
    float s  = v.x + v.y + v.z + v.w;
    float ss = v.x*v.x + v.y*v.y + v.z*v.z + v.w*v.w;
#pragma unroll
    for (int o = 16; o; o >>= 1) {
        s  += __shfl_xor_sync(0xffffffffu, s,  o);
        ss += __shfl_xor_sync(0xffffffffu, ss, o);
    }
    __shared__ float sh[16];
    const int w = threadIdx.x >> 5, l = threadIdx.x & 31;
    if (l == 0) { sh[w] = s; sh[8 + w] = ss; }
    __syncthreads();
    s = 0.f; ss = 0.f;
#pragma unroll
    for (int i = 0; i < 8; i++) { s += sh[i]; ss += sh[8 + i]; }
    const float mean = s * (1.0f / DD);
    const float var  = ss * (1.0f / DD) - mean * mean;
    const float rstd = rsqrtf(var + 1e-3f);

    float4 gg = ((const float4*)g)[threadIdx.x];
    float4 bb = ((const float4*)b)[threadIdx.x];
    float4 o;
    o.x = (v.x - mean) * rstd * gg.x + bb.x;
    o.y = (v.y - mean) * rstd * gg.y + bb.y;
    o.z = (v.z - mean) * rstd * gg.z + bb.z;
    o.w = (v.w - mean) * rstd * gg.w + bb.w;
    ((float4*)(y + (size_t)row * DD))[threadIdx.x] = o;
    if (last && (row % TT) == (TT - 1)) {
        ((float4*)(last + (size_t)(row / TT) * DD))[threadIdx.x] = o;
    }
}

// ---------------- token-shift + lerp mixing (2 or 3 outputs) ----------------
template<int NOUT>
__global__ void __launch_bounds__(256) mix_kernel(
    const float* __restrict__ xn, const float* __restrict__ x0,   // x0: [B,D] initial shift state
    const float* __restrict__ m0, const float* __restrict__ m1, const float* __restrict__ m2,
    float* __restrict__ o0, float* __restrict__ o1, float* __restrict__ o2)
{
    const int i4 = blockIdx.x * blockDim.x + threadIdx.x;   // float4 index over MM*D4
    if (i4 >= MM * D4) return;
    const int d4 = i4 % D4;
    const int bt = i4 / D4;
    const int t = bt % TT, b = bt / TT;
    float4 xc = ((const float4*)xn)[i4];
    float4 xp = (t == 0) ? ((const float4*)x0)[b * D4 + d4]
                         : ((const float4*)xn)[i4 - D4];
    {
        float4 m = ((const float4*)m0)[d4];
        float4 o;
        o.x = xp.x + (xc.x - xp.x) * m.x;
        o.y = xp.y + (xc.y - xp.y) * m.y;
        o.z = xp.z + (xc.z - xp.z) * m.z;
        o.w = xp.w + (xc.w - xp.w) * m.w;
        ((float4*)o0)[i4] = o;
    }
    if (NOUT >= 2) {
        float4 m = ((const float4*)m1)[d4];
        float4 o;
        o.x = xp.x + (xc.x - xp.x) * m.x;
        o.y = xp.y + (xc.y - xp.y) * m.y;
        o.z = xp.z + (xc.z - xp.z) * m.z;
        o.w = xp.w + (xc.w - xp.w) * m.w;
        ((float4*)o1)[i4] = o;
    }
    if (NOUT >= 3) {
        float4 m = ((const float4*)m2)[d4];
        float4 o;
        o.x = xp.x + (xc.x - xp.x) * m.x;
        o.y = xp.y + (xc.y - xp.y) * m.y;
        o.z = xp.z + (xc.z - xp.z) * m.z;
        o.w = xp.w + (xc.w - xp.w) * m.w;
        ((float4*)o2)[i4] = o;
    }
}

// ---------------- WKV scan (serial over T, parallel over B*D channels) ----------------
__global__ void __launch_bounds__(256) wkv_kernel(
    const float* __restrict__ k, const float* __restrict__ v, const float* __restrict__ r,
    const float* __restrict__ a0, const float* __restrict__ b0, const float* __restrict__ p0,
    const float* __restrict__ decay, const float* __restrict__ first,
    float* __restrict__ rw,
    float* __restrict__ aa_o, float* __restrict__ bb_o, float* __restrict__ pp_o)
{
    const int idx = blockIdx.x * blockDim.x + threadIdx.x;  // 0..B*D-1
    if (idx >= BB * DD) return;
    const int d = idx % DD, b = idx / DD;
    float aa = a0[idx], bb = b0[idx], pp = p0[idx];
    const float w = -expf(decay[d]);
    const float u = first[d];
    const size_t base = (size_t)b * TT * DD + d;
    float kt = k[base], vt = v[base];
    for (int t = 0; t < TT; t++) {
        const size_t off = base + (size_t)t * DD;
        float kn = 0.f, vn = 0.f;
        if (t + 1 < TT) { kn = k[off + DD]; vn = v[off + DD]; }   // prefetch
        const float rt = r[off];
        float ww = u + kt;
        float p  = fmaxf(pp, ww);
        float e1 = expf(pp - p), e2 = expf(ww - p);
        float wkv = (e1 * aa + e2 * vt) / (e1 * bb + e2);
        rw[off] = rt * wkv;
        float ww2 = pp + w;
        float p2  = fmaxf(ww2, kt);
        float e1b = expf(ww2 - p2), e2b = expf(kt - p2);
        aa = e1b * aa + e2b * vt;
        bb = e1b * bb + e2b;
        pp = p2;
        kt = kn; vt = vn;
    }
    aa_o[idx] = aa; bb_o[idx] = bb; pp_o[idx] = pp;
}

// ---------------- SGEMM 128x128x8, 8x8 micro-tile, fused epilogues ----------------
// EPI: 0=none, 1=sigmoid, 2=relu^2, 3=acc+X, 4=X + S*acc
template<int EPI>
__global__ void __launch_bounds__(256, 2) sgemm(
    const float* __restrict__ A, const float* __restrict__ Bm, float* __restrict__ C,
    int M, int N, int K,
    const float* __restrict__ X, const float* __restrict__ S)
{
    __shared__ float As[8][128];
    __shared__ float Bs[8][128];
    const int tid  = threadIdx.x;
    const int bm   = blockIdx.y * 128;
    const int bn   = blockIdx.x * 128;
    const int arow = tid >> 1;
    const int acol = (tid & 1) << 2;
    const int brow = tid >> 5;
    const int bcol = (tid & 31) << 2;
    const int ty   = tid >> 4;     // 0..15 (M)
    const int tx   = tid & 15;     // 0..15 (N)

    const float* Ap = A  + (size_t)(bm + arow) * K + acol;
    const float* Bp = Bm + (size_t)brow * N + bn + bcol;

    float4 av = *(const float4*)Ap;
    float4 bv = *(const float4*)Bp;

    float acc[8][8];
#pragma unroll
    for (int i = 0; i < 8; i++)
#pragma unroll
        for (int j = 0; j < 8; j++) acc[i][j] = 0.f;

    for (int k0 = 0; k0 < K; k0 += 8) {
        As[acol+0][arow] = av.x;
        As[acol+1][arow] = av.y;
        As[acol+2][arow] = av.z;
        As[acol+3][arow] = av.w;
        *(float4*)&Bs[brow][bcol] = bv;
        __syncthreads();
        if (k0 + 8 < K) {
            av = *(const float4*)(Ap + k0 + 8);
            bv = *(const float4*)(Bp + (size_t)(k0 + 8) * N);
        }
#pragma unroll
        for (int kk = 0; kk < 8; kk++) {
            float4 a0 = *(const float4*)&As[kk][ty * 4];
            float4 a1 = *(const float4*)&As[kk][ty * 4 + 64];
            float4 b0 = *(const float4*)&Bs[kk][tx * 4];
            float4 b1 = *(const float4*)&Bs[kk][tx * 4 + 64];
            float ar[8] = {a0.x,a0.y,a0.z,a0.w,a1.x,a1.y,a1.z,a1.w};
            float br[8] = {b0.x,b0.y,b0.z,b0.w,b1.x,b1.y,b1.z,b1.w};
#pragma unroll
            for (int i = 0; i < 8; i++)
#pragma unroll
                for (int j = 0; j < 8; j++)
                    acc[i][j] = fmaf(ar[i], br[j], acc[i][j]);
        }
        __syncthreads();
    }

#pragma unroll
    for (int ih = 0; ih < 2; ih++)
#pragma unroll
    for (int i = 0; i < 4; i++) {
        const int row = bm + ih * 64 + ty * 4 + i;
#pragma unroll
        for (int jh = 0; jh < 2; jh++) {
            const int col = bn + jh * 64 + tx * 4;
            const size_t idx = (size_t)row * N + col;
            float4 r4;
            r4.x = acc[ih*4+i][jh*4+0];
            r4.y = acc[ih*4+i][jh*4+1];
            r4.z = acc[ih*4+i][jh*4+2];
            r4.w = acc[ih*4+i][jh*4+3];
            if (EPI == 1) {
                r4.x = 1.f / (1.f + expf(-r4.x));
                r4.y = 1.f / (1.f + expf(-r4.y));
                r4.z = 1.f / (1.f + expf(-r4.z));
                r4.w = 1.f / (1.f + expf(-r4.w));
            } else if (EPI == 2) {
                r4.x = fmaxf(r4.x, 0.f); r4.x *= r4.x;
                r4.y = fmaxf(r4.y, 0.f); r4.y *= r4.y;
                r4.z = fmaxf(r4.z, 0.f); r4.z *= r4.z;
                r4.w = fmaxf(r4.w, 0.f); r4.w *= r4.w;
            } else if (EPI == 3) {
                float4 xv = *(const float4*)&X[idx];
                r4.x += xv.x; r4.y += xv.y; r4.z += xv.z; r4.w += xv.w;
            } else if (EPI == 4) {
                float4 xv = *(const float4*)&X[idx];
                float4 sv = *(const float4*)&S[idx];
                r4.x = xv.x + sv.x * r4.x;
                r4.y = xv.y + sv.y * r4.y;
                r4.z = xv.z + sv.z * r4.z;
                r4.w = xv.w + sv.w * r4.w;
            }
            *(float4*)&C[idx] = r4;
        }
    }
}

// ---------------- host ----------------
extern "C" void kernel_launch(void* const* d_in, const int* in_sizes, int n_in,
                              void* d_out, int out_size)
{
    const float* x        = (const float*)d_in[0];
    const float* att_x    = (const float*)d_in[1];
    const float* att_a    = (const float*)d_in[2];
    const float* att_b    = (const float*)d_in[3];
    const float* att_p    = (const float*)d_in[4];
    const float* ffn_x    = (const float*)d_in[5];
    const float* ln1_g    = (const float*)d_in[6];
    const float* ln1_b    = (const float*)d_in[7];
    const float* ln2_g    = (const float*)d_in[8];
    const float* ln2_b    = (const float*)d_in[9];
    const float* tm_mix_k = (const float*)d_in[10];
    const float* tm_mix_v = (const float*)d_in[11];
    const float* tm_mix_r = (const float*)d_in[12];
    const float* tm_decay = (const float*)d_in[13];
    const float* tm_first = (const float*)d_in[14];
    const float* Wk       = (const float*)d_in[15];
    const float* Wv       = (const float*)d_in[16];
    const float* Wr       = (const float*)d_in[17];
    const float* Wo       = (const float*)d_in[18];
    const float* cm_mix_k = (const float*)d_in[19];
    const float* cm_mix_r = (const float*)d_in[20];
    const float* Ck       = (const float*)d_in[21];
    const float* Cr       = (const float*)d_in[22];
    const float* Cv       = (const float*)d_in[23];

    float* out = (float*)d_out;
    const size_t OFS_XN1 = (size_t)MM * DD;
    const size_t OFS_AA  = OFS_XN1 + (size_t)BB * DD;
    const size_t OFS_BB  = OFS_AA  + (size_t)BB * DD;
    const size_t OFS_PP  = OFS_BB  + (size_t)BB * DD;
    const size_t OFS_XN2 = OFS_PP  + (size_t)BB * DD;

    float *xn, *mk, *mv, *mr, *kk, *vv, *rr, *rw, *x1, *xn2, *mck, *mcr, *kc, *rc;
    cudaGetSymbolAddress((void**)&xn,  g_xn);
    cudaGetSymbolAddress((void**)&mk,  g_mk);
    cudaGetSymbolAddress((void**)&mv,  g_mv);
    cudaGetSymbolAddress((void**)&mr,  g_mr);
    cudaGetSymbolAddress((void**)&kk,  g_k);
    cudaGetSymbolAddress((void**)&vv,  g_v);
    cudaGetSymbolAddress((void**)&rr,  g_r);
    cudaGetSymbolAddress((void**)&rw,  g_rw);
    cudaGetSymbolAddress((void**)&x1,  g_x1);
    cudaGetSymbolAddress((void**)&xn2, g_xn2);
    cudaGetSymbolAddress((void**)&mck, g_mck);
    cudaGetSymbolAddress((void**)&mcr, g_mcr);
    cudaGetSymbolAddress((void**)&kc,  g_kc);
    cudaGetSymbolAddress((void**)&rc,  g_rc);

    const int mixBlocks = (MM * D4 + 255) / 256;

    // 1) ln1(x) -> xn  (+ xn_last output)
    ln_kernel<<<MM, 256>>>(x, ln1_g, ln1_b, xn, out + OFS_XN1);

    // 2) token shift + mix for k/v/r
    mix_kernel<3><<<mixBlocks, 256>>>(xn, att_x, tm_mix_k, tm_mix_v, tm_mix_r, mk, mv, mr);

    // 3) K, V, R GEMMs (R fused sigmoid)
    dim3 gD(DD / 128, MM / 128);
    sgemm<0><<<gD, 256>>>(mk, Wk, kk, MM, DD, DD, nullptr, nullptr);
    sgemm<0><<<gD, 256>>>(mv, Wv, vv, MM, DD, DD, nullptr, nullptr);
    sgemm<1><<<gD, 256>>>(mr, Wr, rr, MM, DD, DD, nullptr, nullptr);

    // 4) WKV scan (fused r*wkv), state outputs
    wkv_kernel<<<(BB * DD) / 256, 256>>>(kk, vv, rr, att_a, att_b, att_p,
                                         tm_decay, tm_first, rw,
                                         out + OFS_AA, out + OFS_BB, out + OFS_PP);

    // 5) x1 = x + (r*wkv) @ Wo
    sgemm<3><<<gD, 256>>>(rw, Wo, x1, MM, DD, DD, x, nullptr);

    // 6) ln2(x1) -> xn2 (+ xn2_last output)
    ln_kernel<<<MM, 256>>>(x1, ln2_g, ln2_b, xn2, out + OFS_XN2);

    // 7) channel-mix token shift
    mix_kernel<2><<<mixBlocks, 256>>>(xn2, ffn_x, cm_mix_k, cm_mix_r, nullptr, mck, mcr, nullptr);

    // 8) kc = relu(mck @ Ck)^2   [M=8192, N=4096, K=1024]
    dim3 gF(FF / 128, MM / 128);
    sgemm<2><<<gF, 256>>>(mck, Ck, kc, MM, FF, DD, nullptr, nullptr);

    // 9) rc = sigmoid(mcr @ Cr)
    sgemm<1><<<gD, 256>>>(mcr, Cr, rc, MM, DD, DD, nullptr, nullptr);

    // 10) out = x1 + rc * (kc @ Cv)   [M=8192, N=1024, K=4096]
    sgemm<4><<<gD, 256>>>(kc, Cv, out, MM, DD, FF, x1, rc);
}

// round 4
// speedup vs baseline: 1.9695x; 1.9695x over previous
#include <cuda_runtime.h>

#define BB 8
#define TT 1024
#define DD 1024
#define FF 4096
#define MM (BB*TT)          // 8192 rows
#define D4 (DD/4)

// ---------------- scratch (static device allocations; allowed) ----------------
__device__ float g_xn [MM*DD];
__device__ float g_mk [MM*DD];
__device__ float g_mv [MM*DD];
__device__ float g_mr [MM*DD];
__device__ float g_k  [MM*DD];
__device__ float g_v  [MM*DD];
__device__ float g_r  [MM*DD];
__device__ float g_rw [MM*DD];   // r * wkv
__device__ float g_x1 [MM*DD];
__device__ float g_xn2[MM*DD];
__device__ float g_mck[MM*DD];
__device__ float g_mcr[MM*DD];
__device__ float g_kc [MM*FF];   // relu(.)^2 of channel-mix key
__device__ float g_rc [MM*DD];

// ---------------- LayerNorm: one block per row, D=1024, 256 threads ----------------
__global__ void __launch_bounds__(256) ln_kernel(
    const float* __restrict__ x, const float* __restrict__ g,
    const float* __restrict__ b, float* __restrict__ y,
    float* __restrict__ last)
{
    const int row = blockIdx.x;
    const float4* xr = (const float4*)(x + (size_t)row * DD);
    float4 v = xr[threadIdx.x];
    float s  = v.x + v.y + v.z + v.w;
    float ss = v.x*v.x + v.y*v.y + v.z*v.z + v.w*v.w;
#pragma unroll
    for (int o = 16; o; o >>= 1) {
        s  += __shfl_xor_sync(0xffffffffu, s,  o);
        ss += __shfl_xor_sync(0xffffffffu, ss, o);
    }
    __shared__ float sh[16];
    const int w = threadIdx.x >> 5, l = threadIdx.x & 31;
    if (l == 0) { sh[w] = s; sh[8 + w] = ss; }
    __syncthreads();
    s = 0.f; ss = 0.f;
#pragma unroll
    for (int i = 0; i < 8; i++) { s += sh[i]; ss += sh[8 + i]; }
    const float mean = s * (1.0f / DD);
    const float var  = ss * (1.0f / DD) - mean * mean;
    const float rstd = rsqrtf(var + 1e-3f);

    float4 gg = ((const float4*)g)[threadIdx.x];
    float4 bb = ((const float4*)b)[threadIdx.x];
    float4 o;
    o.x = (v.x - mean) * rstd * gg.x + bb.x;
    o.y = (v.y - mean) * rstd * gg.y + bb.y;
    o.z = (v.z - mean) * rstd * gg.z + bb.z;
    o.w = (v.w - mean) * rstd * gg.w + bb.w;
    ((float4*)(y + (size_t)row * DD))[threadIdx.x] = o;
    if (last && (row % TT) == (TT - 1)) {
        ((float4*)(last + (size_t)(row / TT) * DD))[threadIdx.x] = o;
    }
}

// ---------------- token-shift + lerp mixing (2 or 3 outputs) ----------------
template<int NOUT>
__global__ void __launch_bounds__(256) mix_kernel(
    const float* __restrict__ xn, const float* __restrict__ x0,
    const float* __restrict__ m0, const float* __restrict__ m1, const float* __restrict__ m2,
    float* __restrict__ o0, float* __restrict__ o1, float* __restrict__ o2)
{
    const int i4 = blockIdx.x * blockDim.x + threadIdx.x;
    if (i4 >= MM * D4) return;
    const int d4 = i4 % D4;
    const int bt = i4 / D4;
    const int t = bt % TT, b = bt / TT;
    float4 xc = ((const float4*)xn)[i4];
    float4 xp = (t == 0) ? ((const float4*)x0)[b * D4 + d4]
                         : ((const float4*)xn)[i4 - D4];
    {
        float4 m = ((const float4*)m0)[d4];
        float4 o;
        o.x = xp.x + (xc.x - xp.x) * m.x;
        o.y = xp.y + (xc.y - xp.y) * m.y;
        o.z = xp.z + (xc.z - xp.z) * m.z;
        o.w = xp.w + (xc.w - xp.w) * m.w;
        ((float4*)o0)[i4] = o;
    }
    if (NOUT >= 2) {
        float4 m = ((const float4*)m1)[d4];
        float4 o;
        o.x = xp.x + (xc.x - xp.x) * m.x;
        o.y = xp.y + (xc.y - xp.y) * m.y;
        o.z = xp.z + (xc.z - xp.z) * m.z;
        o.w = xp.w + (xc.w - xp.w) * m.w;
        ((float4*)o1)[i4] = o;
    }
    if (NOUT >= 3) {
        float4 m = ((const float4*)m2)[d4];
        float4 o;
        o.x = xp.x + (xc.x - xp.x) * m.x;
        o.y = xp.y + (xc.y - xp.y) * m.y;
        o.z = xp.z + (xc.z - xp.z) * m.z;
        o.w = xp.w + (xc.w - xp.w) * m.w;
        ((float4*)o2)[i4] = o;
    }
}

// ---------------- WKV scan ----------------
__global__ void __launch_bounds__(256) wkv_kernel(
    const float* __restrict__ k, const float* __restrict__ v, const float* __restrict__ r,
    const float* __restrict__ a0, const float* __restrict__ b0, const float* __restrict__ p0,
    const float* __restrict__ decay, const float* __restrict__ first,
    float* __restrict__ rw,
    float* __restrict__ aa_o, float* __restrict__ bb_o, float* __restrict__ pp_o)
{
    const int idx = blockIdx.x * blockDim.x + threadIdx.x;
    if (idx >= BB * DD) return;
    const int d = idx % DD, b = idx / DD;
    float aa = a0[idx], bb = b0[idx], pp = p0[idx];
    const float w = -expf(decay[d]);
    const float u = first[d];
    const size_t base = (size_t)b * TT * DD + d;
    float kt = k[base], vt = v[base];
    for (int t = 0; t < TT; t++) {
        const size_t off = base + (size_t)t * DD;
        float kn = 0.f, vn = 0.f;
        if (t + 1 < TT) { kn = k[off + DD]; vn = v[off + DD]; }
        const float rt = r[off];
        float ww = u + kt;
        float p  = fmaxf(pp, ww);
        float e1 = expf(pp - p), e2 = expf(ww - p);
        float wkv = (e1 * aa + e2 * vt) / (e1 * bb + e2);
        rw[off] = rt * wkv;
        float ww2 = pp + w;
        float p2  = fmaxf(ww2, kt);
        float e1b = expf(ww2 - p2), e2b = expf(kt - p2);
        aa = e1b * aa + e2b * vt;
        bb = e1b * bb + e2b;
        pp = p2;
        kt = kn; vt = vn;
    }
    aa_o[idx] = aa; bb_o[idx] = bb; pp_o[idx] = pp;
}

// ---------------- TF32 tensor-core GEMM: 128x128x16, mma.m16n8k8 ----------------
// Smem holds pre-permuted mma fragments, XOR-swizzled for conflict-free STS/LDS.
// EPI: 0=none, 1=sigmoid, 2=relu^2, 3=acc+X, 4=X + S*acc

__device__ __forceinline__ unsigned f2tf32(float f) {
    unsigned u;
    asm("cvt.rna.tf32.f32 %0, %1;" : "=r"(u) : "f"(f));
    return u;
}

__device__ __forceinline__ void mma_tf32(
    float& c0, float& c1, float& c2, float& c3,
    unsigned a0, unsigned a1, unsigned a2, unsigned a3,
    unsigned b0, unsigned b1)
{
    asm volatile(
        "mma.sync.aligned.m16n8k8.row.col.f32.tf32.tf32.f32 "
        "{%0,%1,%2,%3}, {%4,%5,%6,%7}, {%8,%9}, {%0,%1,%2,%3};\n"
        : "+f"(c0), "+f"(c1), "+f"(c2), "+f"(c3)
        : "r"(a0), "r"(a1), "r"(a2), "r"(a3), "r"(b0), "r"(b1));
}

template<int EPI>
__global__ void __launch_bounds__(256, 2) tgemm(
    const float* __restrict__ A, const float* __restrict__ Bm, float* __restrict__ C,
    int M, int N, int K,
    const float* __restrict__ X, const float* __restrict__ S)
{
    // Fragment-layout smem. A: [mt(8)*2+ks][reg(4)][lane(32)] ; B: [nt(16)*2+ks][reg(2)][lane(32)]
    __shared__ __align__(16) unsigned As[2048];   // 8 KB
    __shared__ __align__(16) unsigned Bs[2048];   // 8 KB

    const int tid  = threadIdx.x;
    const int lane = tid & 31;
    const int warp = tid >> 5;
    const int wm   = warp >> 2;     // 0..1
    const int wn   = warp & 3;      // 0..3
    const int bm   = blockIdx.y * 128;
    const int bn   = blockIdx.x * 128;

    // ---- global A mapping: f4 = i*256 + tid; row = i*64 + (tid>>2); kq = (tid&3)*4 ----
    const int ra  = tid >> 2;           // 0..63
    const int kqa = (tid & 3) << 2;     // 0,4,8,12
    // ---- global B mapping: k = i*8 + warp; nq = lane*4 ----
    // Precompute permuted STS offsets (constant per thread).
    int offA[2], offB[2][4];
#pragma unroll
    for (int i = 0; i < 2; i++) {
        const int m  = i * 64 + ra;
        const int r  = m & 15;
        const int mt = m >> 4;
        const int ks = kqa >> 3;            // 0 or 1
        const int ch = (kqa >> 2) & 1;      // c>>2 bit
        const int reg = (r >> 3) | (ch << 1);
        const int swz = (reg << 2) ^ (ks << 4);
        offA[i] = (((mt << 1) | ks) << 7) + (reg << 5) + ((((r & 7) << 2)) ^ swz);
        // low 2 bits zero -> uint4 store of e=0..3
        const int kB  = i * 8 + warp;       // 0..15
        const int ksB = kB >> 3;
        const int regB = (kB >> 2) & 1;
        const int nt  = lane >> 1;          // 0..15
        const int swzB = (((nt & 7) << 2)) ^ (((nt >> 3) & 1) << 1);
#pragma unroll
        for (int e = 0; e < 4; e++) {
            const int n = (lane << 2) + e;
            const int lane_s = ((n & 7) << 2) | (kB & 3);
            offB[i][e] = (((nt << 1) | ksB) << 6) + (regB << 5) + (lane_s ^ swzB);
        }
    }

    const float* Ap0 = A + (size_t)(bm + ra) * K + kqa;
    const float* Ap1 = A + (size_t)(bm + 64 + ra) * K + kqa;
    const float* Bp0 = Bm + (size_t)warp * N + bn + (lane << 2);
    const float* Bp1 = Bm + (size_t)(warp + 8) * N + bn + (lane << 2);

    float4 avr[2], bvr[2];
    avr[0] = *(const float4*)Ap0;
    avr[1] = *(const float4*)Ap1;
    bvr[0] = *(const float4*)Bp0;
    bvr[1] = *(const float4*)Bp1;

    float acc[4][4][4];
#pragma unroll
    for (int i = 0; i < 4; i++)
#pragma unroll
        for (int j = 0; j < 4; j++)
#pragma unroll
            for (int e = 0; e < 4; e++) acc[i][j][e] = 0.f;

    for (int k0 = 0; k0 < K; k0 += 16) {
        // ---- stage to smem (tf32-converted, fragment-permuted) ----
#pragma unroll
        for (int i = 0; i < 2; i++) {
            uint4 pa;
            pa.x = f2tf32(avr[i].x); pa.y = f2tf32(avr[i].y);
            pa.z = f2tf32(avr[i].z); pa.w = f2tf32(avr[i].w);
            *(uint4*)&As[offA[i]] = pa;
            Bs[offB[i][0]] = f2tf32(bvr[i].x);
            Bs[offB[i][1]] = f2tf32(bvr[i].y);
            Bs[offB[i][2]] = f2tf32(bvr[i].z);
            Bs[offB[i][3]] = f2tf32(bvr[i].w);
        }
        __syncthreads();

        // ---- prefetch next K-slab ----
        if (k0 + 16 < K) {
            avr[0] = *(const float4*)(Ap0 + k0 + 16);
            avr[1] = *(const float4*)(Ap1 + k0 + 16);
            bvr[0] = *(const float4*)(Bp0 + (size_t)(k0 + 16) * N);
            bvr[1] = *(const float4*)(Bp1 + (size_t)(k0 + 16) * N);
        }

        // ---- compute: 2 k-steps of m16n8k8, 4x4 tiles per warp ----
#pragma unroll
        for (int ks = 0; ks < 2; ks++) {
            unsigned af[4][4], bf[4][2];
#pragma unroll
            for (int mt = 0; mt < 4; mt++) {
                const int mtg = wm * 4 + mt;
                const int base = (((mtg << 1) | ks) << 7);
#pragma unroll
                for (int reg = 0; reg < 4; reg++)
                    af[mt][reg] = As[base + (reg << 5) + (lane ^ (reg << 2) ^ (ks << 4))];
            }
#pragma unroll
            for (int nt = 0; nt < 4; nt++) {
                const int ntg = wn * 4 + nt;
                const int swzB = (((ntg & 7) << 2)) ^ (((ntg >> 3) & 1) << 1);
                const int base = (((ntg << 1) | ks) << 6);
#pragma unroll
                for (int reg = 0; reg < 2; reg++)
                    bf[nt][reg] = Bs[base + (reg << 5) + (lane ^ swzB)];
            }
#pragma unroll
            for (int mt = 0; mt < 4; mt++)
#pragma unroll
                for (int nt = 0; nt < 4; nt++)
                    mma_tf32(acc[mt][nt][0], acc[mt][nt][1], acc[mt][nt][2], acc[mt][nt][3],
                             af[mt][0], af[mt][1], af[mt][2], af[mt][3],
                             bf[nt][0], bf[nt][1]);
        }
        __syncthreads();
    }

    // ---- epilogue: c0,c1 @ (row, col), c2,c3 @ (row+8, col) ----
    const int rbase = bm + wm * 64 + (lane >> 2);
    const int cbase = bn + wn * 32 + ((lane & 3) << 1);
#pragma unroll
    for (int mt = 0; mt < 4; mt++) {
#pragma unroll
        for (int h = 0; h < 2; h++) {
            const int row = rbase + mt * 16 + h * 8;
#pragma unroll
            for (int nt = 0; nt < 4; nt++) {
                const int col = cbase + nt * 8;
                const size_t idx = (size_t)row * N + col;
                float v0 = acc[mt][nt][h * 2 + 0];
                float v1 = acc[mt][nt][h * 2 + 1];
                if (EPI == 1) {
                    v0 = 1.f / (1.f + expf(-v0));
                    v1 = 1.f / (1.f + expf(-v1));
                } else if (EPI == 2) {
                    v0 = fmaxf(v0, 0.f); v0 *= v0;
                    v1 = fmaxf(v1, 0.f); v1 *= v1;
                } else if (EPI == 3) {
                    float2 xv = *(const float2*)&X[idx];
                    v0 += xv.x; v1 += xv.y;
                } else if (EPI == 4) {
                    float2 xv = *(const float2*)&X[idx];
                    float2 sv = *(const float2*)&S[idx];
                    v0 = xv.x + sv.x * v0;
                    v1 = xv.y + sv.y * v1;
                }
                float2 o; o.x = v0; o.y = v1;
                *(float2*)&C[idx] = o;
            }
        }
    }
}

// ---------------- host ----------------
extern "C" void kernel_launch(void* const* d_in, const int* in_sizes, int n_in,
                              void* d_out, int out_size)
{
    const float* x        = (const float*)d_in[0];
    const float* att_x    = (const float*)d_in[1];
    const float* att_a    = (const float*)d_in[2];
    const float* att_b    = (const float*)d_in[3];
    const float* att_p    = (const float*)d_in[4];
    const float* ffn_x    = (const float*)d_in[5];
    const float* ln1_g    = (const float*)d_in[6];
    const float* ln1_b    = (const float*)d_in[7];
    const float* ln2_g    = (const float*)d_in[8];
    const float* ln2_b    = (const float*)d_in[9];
    const float* tm_mix_k = (const float*)d_in[10];
    const float* tm_mix_v = (const float*)d_in[11];
    const float* tm_mix_r = (const float*)d_in[12];
    const float* tm_decay = (const float*)d_in[13];
    const float* tm_first = (const float*)d_in[14];
    const float* Wk       = (const float*)d_in[15];
    const float* Wv       = (const float*)d_in[16];
    const float* Wr       = (const float*)d_in[17];
    const float* Wo       = (const float*)d_in[18];
    const float* cm_mix_k = (const float*)d_in[19];
    const float* cm_mix_r = (const float*)d_in[20];
    const float* Ck       = (const float*)d_in[21];
    const float* Cr       = (const float*)d_in[22];
    const float* Cv       = (const float*)d_in[23];

    float* out = (float*)d_out;
    const size_t OFS_XN1 = (size_t)MM * DD;
    const size_t OFS_AA  = OFS_XN1 + (size_t)BB * DD;
    const size_t OFS_BB  = OFS_AA  + (size_t)BB * DD;
    const size_t OFS_PP  = OFS_BB  + (size_t)BB * DD;
    const size_t OFS_XN2 = OFS_PP  + (size_t)BB * DD;

    float *xn, *mk, *mv, *mr, *kk, *vv, *rr, *rw, *x1, *xn2, *mck, *mcr, *kc, *rc;
    cudaGetSymbolAddress((void**)&xn,  g_xn);
    cudaGetSymbolAddress((void**)&mk,  g_mk);
    cudaGetSymbolAddress((void**)&mv,  g_mv);
    cudaGetSymbolAddress((void**)&mr,  g_mr);
    cudaGetSymbolAddress((void**)&kk,  g_k);
    cudaGetSymbolAddress((void**)&vv,  g_v);
    cudaGetSymbolAddress((void**)&rr,  g_r);
    cudaGetSymbolAddress((void**)&rw,  g_rw);
    cudaGetSymbolAddress((void**)&x1,  g_x1);
    cudaGetSymbolAddress((void**)&xn2, g_xn2);
    cudaGetSymbolAddress((void**)&mck, g_mck);
    cudaGetSymbolAddress((void**)&mcr, g_mcr);
    cudaGetSymbolAddress((void**)&kc,  g_kc);
    cudaGetSymbolAddress((void**)&rc,  g_rc);

    const int mixBlocks = (MM * D4 + 255) / 256;

    // 1) ln1(x) -> xn  (+ xn_last output)
    ln_kernel<<<MM, 256>>>(x, ln1_g, ln1_b, xn, out + OFS_XN1);

    // 2) token shift + mix for k/v/r
    mix_kernel<3><<<mixBlocks, 256>>>(xn, att_x, tm_mix_k, tm_mix_v, tm_mix_r, mk, mv, mr);

    // 3) K, V, R GEMMs (R fused sigmoid)
    dim3 gD(DD / 128, MM / 128);
    tgemm<0><<<gD, 256>>>(mk, Wk, kk, MM, DD, DD, nullptr, nullptr);
    tgemm<0><<<gD, 256>>>(mv, Wv, vv, MM, DD, DD, nullptr, nullptr);
    tgemm<1><<<gD, 256>>>(mr, Wr, rr, MM, DD, DD, nullptr, nullptr);

    // 4) WKV scan (fused r*wkv), state outputs
    wkv_kernel<<<(BB * DD) / 256, 256>>>(kk, vv, rr, att_a, att_b, att_p,
                                         tm_decay, tm_first, rw,
                                         out + OFS_AA, out + OFS_BB, out + OFS_PP);

    // 5) x1 = x + (r*wkv) @ Wo
    tgemm<3><<<gD, 256>>>(rw, Wo, x1, MM, DD, DD, x, nullptr);

    // 6) ln2(x1) -> xn2 (+ xn2_last output)
    ln_kernel<<<MM, 256>>>(x1, ln2_g, ln2_b, xn2, out + OFS_XN2);

    // 7) channel-mix token shift
    mix_kernel<2><<<mixBlocks, 256>>>(xn2, ffn_x, cm_mix_k, cm_mix_r, nullptr, mck, mcr, nullptr);

    // 8) kc = relu(mck @ Ck)^2   [M=8192, N=4096, K=1024]
    dim3 gF(FF / 128, MM / 128);
    tgemm<2><<<gF, 256>>>(mck, Ck, kc, MM, FF, DD, nullptr, nullptr);

    // 9) rc = sigmoid(mcr @ Cr)
    tgemm<1><<<gD, 256>>>(mcr, Cr, rc, MM, DD, DD, nullptr, nullptr);

    // 10) out = x1 + rc * (kc @ Cv)   [M=8192, N=1024, K=4096]
    tgemm<4><<<gD, 256>>>(kc, Cv, out, MM, DD, FF, x1, rc);
}

// round 5
// speedup vs baseline: 2.2691x; 1.1521x over previous
#include <cuda_runtime.h>

#define BB 8
#define TT 1024
#define DD 1024
#define FF 4096
#define MM (BB*TT)          // 8192 rows
#define D4 (DD/4)

// ---------------- scratch (static device allocations; allowed) ----------------
__device__ float g_xn [MM*DD];
__device__ float g_mk [MM*DD];
__device__ float g_mv [MM*DD];
__device__ float g_mr [MM*DD];
__device__ float g_k  [MM*DD];
__device__ float g_v  [MM*DD];
__device__ float g_r  [MM*DD];
__device__ float g_rw [MM*DD];   // r * wkv
__device__ float g_x1 [MM*DD];
__device__ float g_xn2[MM*DD];
__device__ float g_mck[MM*DD];
__device__ float g_mcr[MM*DD];
__device__ float g_kc [MM*FF];   // relu(.)^2 of channel-mix key
__device__ float g_rc [MM*DD];

// ---------------- LayerNorm: one block per row, D=1024, 256 threads ----------------
__global__ void __launch_bounds__(256) ln_kernel(
    const float* __restrict__ x, const float* __restrict__ g,
    const float* __restrict__ b, float* __restrict__ y,
    float* __restrict__ last)
{
    const int row = blockIdx.x;
    const float4* xr = (const float4*)(x + (size_t)row * DD);
    float4 v = xr[threadIdx.x];
    float s  = v.x + v.y + v.z + v.w;
    float ss = v.x*v.x + v.y*v.y + v.z*v.z + v.w*v.w;
#pragma unroll
    for (int o = 16; o; o >>= 1) {
        s  += __shfl_xor_sync(0xffffffffu, s,  o);
        ss += __shfl_xor_sync(0xffffffffu, ss, o);
    }
    __shared__ float sh[16];
    const int w = threadIdx.x >> 5, l = threadIdx.x & 31;
    if (l == 0) { sh[w] = s; sh[8 + w] = ss; }
    __syncthreads();
    s = 0.f; ss = 0.f;
#pragma unroll
    for (int i = 0; i < 8; i++) { s += sh[i]; ss += sh[8 + i]; }
    const float mean = s * (1.0f / DD);
    const float var  = ss * (1.0f / DD) - mean * mean;
    const float rstd = rsqrtf(var + 1e-3f);

    float4 gg = ((const float4*)g)[threadIdx.x];
    float4 bb = ((const float4*)b)[threadIdx.x];
    float4 o;
    o.x = (v.x - mean) * rstd * gg.x + bb.x;
    o.y = (v.y - mean) * rstd * gg.y + bb.y;
    o.z = (v.z - mean) * rstd * gg.z + bb.z;
    o.w = (v.w - mean) * rstd * gg.w + bb.w;
    ((float4*)(y + (size_t)row * DD))[threadIdx.x] = o;
    if (last && (row % TT) == (TT - 1)) {
        ((float4*)(last + (size_t)(row / TT) * DD))[threadIdx.x] = o;
    }
}

// ---------------- token-shift + lerp mixing (2 or 3 outputs) ----------------
template<int NOUT>
__global__ void __launch_bounds__(256) mix_kernel(
    const float* __restrict__ xn, const float* __restrict__ x0,
    const float* __restrict__ m0, const float* __restrict__ m1, const float* __restrict__ m2,
    float* __restrict__ o0, float* __restrict__ o1, float* __restrict__ o2)
{
    const int i4 = blockIdx.x * blockDim.x + threadIdx.x;
    if (i4 >= MM * D4) return;
    const int d4 = i4 % D4;
    const int bt = i4 / D4;
    const int t = bt % TT, b = bt / TT;
    float4 xc = ((const float4*)xn)[i4];
    float4 xp = (t == 0) ? ((const float4*)x0)[b * D4 + d4]
                         : ((const float4*)xn)[i4 - D4];
    {
        float4 m = ((const float4*)m0)[d4];
        float4 o;
        o.x = xp.x + (xc.x - xp.x) * m.x;
        o.y = xp.y + (xc.y - xp.y) * m.y;
        o.z = xp.z + (xc.z - xp.z) * m.z;
        o.w = xp.w + (xc.w - xp.w) * m.w;
        ((float4*)o0)[i4] = o;
    }
    if (NOUT >= 2) {
        float4 m = ((const float4*)m1)[d4];
        float4 o;
        o.x = xp.x + (xc.x - xp.x) * m.x;
        o.y = xp.y + (xc.y - xp.y) * m.y;
        o.z = xp.z + (xc.z - xp.z) * m.z;
        o.w = xp.w + (xc.w - xp.w) * m.w;
        ((float4*)o1)[i4] = o;
    }
    if (NOUT >= 3) {
        float4 m = ((const float4*)m2)[d4];
        float4 o;
        o.x = xp.x + (xc.x - xp.x) * m.x;
        o.y = xp.y + (xc.y - xp.y) * m.y;
        o.z = xp.z + (xc.z - xp.z) * m.z;
        o.w = xp.w + (xc.w - xp.w) * m.w;
        ((float4*)o2)[i4] = o;
    }
}

// ---------------- WKV scan: 4-deep prefetch, 64-thread blocks ----------------
__global__ void __launch_bounds__(64) wkv_kernel(
    const float* __restrict__ k, const float* __restrict__ v, const float* __restrict__ r,
    const float* __restrict__ a0, const float* __restrict__ b0, const float* __restrict__ p0,
    const float* __restrict__ decay, const float* __restrict__ first,
    float* __restrict__ rw,
    float* __restrict__ aa_o, float* __restrict__ bb_o, float* __restrict__ pp_o)
{
    const int idx = blockIdx.x * blockDim.x + threadIdx.x;
    if (idx >= BB * DD) return;
    const int d = idx % DD, b = idx / DD;
    float aa = a0[idx], bb = b0[idx], pp = p0[idx];
    const float w = -expf(decay[d]);
    const float u = first[d];
    const size_t base = (size_t)b * TT * DD + d;

    float kb[4], vb[4], rb[4];
#pragma unroll
    for (int j = 0; j < 4; j++) {
        kb[j] = k[base + (size_t)j * DD];
        vb[j] = v[base + (size_t)j * DD];
        rb[j] = r[base + (size_t)j * DD];
    }

    for (int t0 = 0; t0 < TT; t0 += 4) {
        float kn[4], vn[4], rn[4];
        if (t0 + 4 < TT) {
#pragma unroll
            for (int j = 0; j < 4; j++) {
                const size_t off = base + (size_t)(t0 + 4 + j) * DD;
                kn[j] = k[off]; vn[j] = v[off]; rn[j] = r[off];
            }
        } else {
#pragma unroll
            for (int j = 0; j < 4; j++) { kn[j] = 0.f; vn[j] = 0.f; rn[j] = 0.f; }
        }
#pragma unroll
        for (int j = 0; j < 4; j++) {
            const size_t off = base + (size_t)(t0 + j) * DD;
            const float kt = kb[j], vt = vb[j], rt = rb[j];
            float ww = u + kt;
            float p  = fmaxf(pp, ww);
            float e1 = expf(pp - p), e2 = expf(ww - p);
            float wkv = (e1 * aa + e2 * vt) / (e1 * bb + e2);
            rw[off] = rt * wkv;
            float ww2 = pp + w;
            float p2  = fmaxf(ww2, kt);
            float e1b = expf(ww2 - p2), e2b = expf(kt - p2);
            aa = e1b * aa + e2b * vt;
            bb = e1b * bb + e2b;
            pp = p2;
        }
#pragma unroll
        for (int j = 0; j < 4; j++) { kb[j] = kn[j]; vb[j] = vn[j]; rb[j] = rn[j]; }
    }
    aa_o[idx] = aa; bb_o[idx] = bb; pp_o[idx] = pp;
}

// ---------------- TF32 tensor-core GEMM: 128x128x16, mma.m16n8k8 ----------------
// Double-buffered fragment-layout smem (ONE barrier per K-slab).
// EPI: 0=none, 1=sigmoid, 2=relu^2, 3=acc+X, 4=X + S*acc

__device__ __forceinline__ unsigned f2tf32(float f) {
    unsigned u;
    asm("cvt.rna.tf32.f32 %0, %1;" : "=r"(u) : "f"(f));
    return u;
}

__device__ __forceinline__ void mma_tf32(
    float& c0, float& c1, float& c2, float& c3,
    unsigned a0, unsigned a1, unsigned a2, unsigned a3,
    unsigned b0, unsigned b1)
{
    asm volatile(
        "mma.sync.aligned.m16n8k8.row.col.f32.tf32.tf32.f32 "
        "{%0,%1,%2,%3}, {%4,%5,%6,%7}, {%8,%9}, {%0,%1,%2,%3};\n"
        : "+f"(c0), "+f"(c1), "+f"(c2), "+f"(c3)
        : "r"(a0), "r"(a1), "r"(a2), "r"(a3), "r"(b0), "r"(b1));
}

template<int EPI>
__global__ void __launch_bounds__(256, 2) tgemm(
    const float* __restrict__ A, const float* __restrict__ Bm, float* __restrict__ C,
    int M, int N, int K,
    const float* __restrict__ X, const float* __restrict__ S)
{
    // Two stages: stage bit adds 2048 words (8 KB) each.
    __shared__ __align__(16) unsigned As[4096];   // 16 KB
    __shared__ __align__(16) unsigned Bs[4096];   // 16 KB

    const int tid  = threadIdx.x;
    const int lane = tid & 31;
    const int warp = tid >> 5;
    const int wm   = warp >> 2;     // 0..1
    const int wn   = warp & 3;      // 0..3
    const int bm   = blockIdx.y * 128;
    const int bn   = blockIdx.x * 128;

    const int ra  = tid >> 2;           // 0..63
    const int kqa = (tid & 3) << 2;     // 0,4,8,12
    int offA[2], offB[2][4];
#pragma unroll
    for (int i = 0; i < 2; i++) {
        const int m  = i * 64 + ra;
        const int r  = m & 15;
        const int mt = m >> 4;
        const int ks = kqa >> 3;            // 0 or 1
        const int ch = (kqa >> 2) & 1;      // c>>2 bit
        const int reg = (r >> 3) | (ch << 1);
        const int swz = (reg << 2) ^ (ks << 4);
        offA[i] = (((mt << 1) | ks) << 7) + (reg << 5) + ((((r & 7) << 2)) ^ swz);
        const int kB  = i * 8 + warp;       // 0..15
        const int ksB = kB >> 3;
        const int regB = (kB >> 2) & 1;
        const int nt  = lane >> 1;          // 0..15
        const int swzB = (((nt & 7) << 2)) ^ (((nt >> 3) & 1) << 1);
#pragma unroll
        for (int e = 0; e < 4; e++) {
            const int n = (lane << 2) + e;
            const int lane_s = ((n & 7) << 2) | (kB & 3);
            offB[i][e] = (((nt << 1) | ksB) << 6) + (regB << 5) + (lane_s ^ swzB);
        }
    }

    const float* Ap0 = A + (size_t)(bm + ra) * K + kqa;
    const float* Ap1 = A + (size_t)(bm + 64 + ra) * K + kqa;
    const float* Bp0 = Bm + (size_t)warp * N + bn + (lane << 2);
    const float* Bp1 = Bm + (size_t)(warp + 8) * N + bn + (lane << 2);

    float4 avr[2], bvr[2];
    avr[0] = *(const float4*)Ap0;
    avr[1] = *(const float4*)Ap1;
    bvr[0] = *(const float4*)Bp0;
    bvr[1] = *(const float4*)Bp1;

    float acc[4][4][4];
#pragma unroll
    for (int i = 0; i < 4; i++)
#pragma unroll
        for (int j = 0; j < 4; j++)
#pragma unroll
            for (int e = 0; e < 4; e++) acc[i][j][e] = 0.f;

    for (int k0 = 0; k0 < K; k0 += 16) {
        const int sb = ((k0 >> 4) & 1) << 11;     // stage word-offset: 0 / 2048
        // ---- stage to smem (tf32-converted, fragment-permuted) ----
#pragma unroll
        for (int i = 0; i < 2; i++) {
            uint4 pa;
            pa.x = f2tf32(avr[i].x); pa.y = f2tf32(avr[i].y);
            pa.z = f2tf32(avr[i].z); pa.w = f2tf32(avr[i].w);
            *(uint4*)&As[sb + offA[i]] = pa;
            Bs[sb + offB[i][0]] = f2tf32(bvr[i].x);
            Bs[sb + offB[i][1]] = f2tf32(bvr[i].y);
            Bs[sb + offB[i][2]] = f2tf32(bvr[i].z);
            Bs[sb + offB[i][3]] = f2tf32(bvr[i].w);
        }
        __syncthreads();   // the ONLY barrier per slab (double-buffered)

        // ---- prefetch next K-slab while computing this one ----
        if (k0 + 16 < K) {
            avr[0] = *(const float4*)(Ap0 + k0 + 16);
            avr[1] = *(const float4*)(Ap1 + k0 + 16);
            bvr[0] = *(const float4*)(Bp0 + (size_t)(k0 + 16) * N);
            bvr[1] = *(const float4*)(Bp1 + (size_t)(k0 + 16) * N);
        }

        // ---- compute: 2 k-steps of m16n8k8, 4x4 tiles per warp ----
        const unsigned* Asb = As + sb;
        const unsigned* Bsb = Bs + sb;
#pragma unroll
        for (int ks = 0; ks < 2; ks++) {
            unsigned af[4][4], bf[4][2];
#pragma unroll
            for (int mt = 0; mt < 4; mt++) {
                const int mtg = wm * 4 + mt;
                const int base = (((mtg << 1) | ks) << 7);
#pragma unroll
                for (int reg = 0; reg < 4; reg++)
                    af[mt][reg] = Asb[base + (reg << 5) + (lane ^ (reg << 2) ^ (ks << 4))];
            }
#pragma unroll
            for (int nt = 0; nt < 4; nt++) {
                const int ntg = wn * 4 + nt;
                const int swzB = (((ntg & 7) << 2)) ^ (((ntg >> 3) & 1) << 1);
                const int base = (((ntg << 1) | ks) << 6);
#pragma unroll
                for (int reg = 0; reg < 2; reg++)
                    bf[nt][reg] = Bsb[base + (reg << 5) + (lane ^ swzB)];
            }
#pragma unroll
            for (int mt = 0; mt < 4; mt++)
#pragma unroll
                for (int nt = 0; nt < 4; nt++)
                    mma_tf32(acc[mt][nt][0], acc[mt][nt][1], acc[mt][nt][2], acc[mt][nt][3],
                             af[mt][0], af[mt][1], af[mt][2], af[mt][3],
                             bf[nt][0], bf[nt][1]);
        }
        // no trailing barrier: next iteration writes the other stage
    }

    // ---- epilogue ----
    const int rbase = bm + wm * 64 + (lane >> 2);
    const int cbase = bn + wn * 32 + ((lane & 3) << 1);
#pragma unroll
    for (int mt = 0; mt < 4; mt++) {
#pragma unroll
        for (int h = 0; h < 2; h++) {
            const int row = rbase + mt * 16 + h * 8;
#pragma unroll
            for (int nt = 0; nt < 4; nt++) {
                const int col = cbase + nt * 8;
                const size_t idx = (size_t)row * N + col;
                float v0 = acc[mt][nt][h * 2 + 0];
                float v1 = acc[mt][nt][h * 2 + 1];
                if (EPI == 1) {
                    v0 = 1.f / (1.f + expf(-v0));
                    v1 = 1.f / (1.f + expf(-v1));
                } else if (EPI == 2) {
                    v0 = fmaxf(v0, 0.f); v0 *= v0;
                    v1 = fmaxf(v1, 0.f); v1 *= v1;
                } else if (EPI == 3) {
                    float2 xv = *(const float2*)&X[idx];
                    v0 += xv.x; v1 += xv.y;
                } else if (EPI == 4) {
                    float2 xv = *(const float2*)&X[idx];
                    float2 sv = *(const float2*)&S[idx];
                    v0 = xv.x + sv.x * v0;
                    v1 = xv.y + sv.y * v1;
                }
                float2 o; o.x = v0; o.y = v1;
                *(float2*)&C[idx] = o;
            }
        }
    }
}

// ---------------- host ----------------
extern "C" void kernel_launch(void* const* d_in, const int* in_sizes, int n_in,
                              void* d_out, int out_size)
{
    const float* x        = (const float*)d_in[0];
    const float* att_x    = (const float*)d_in[1];
    const float* att_a    = (const float*)d_in[2];
    const float* att_b    = (const float*)d_in[3];
    const float* att_p    = (const float*)d_in[4];
    const float* ffn_x    = (const float*)d_in[5];
    const float* ln1_g    = (const float*)d_in[6];
    const float* ln1_b    = (const float*)d_in[7];
    const float* ln2_g    = (const float*)d_in[8];
    const float* ln2_b    = (const float*)d_in[9];
    const float* tm_mix_k = (const float*)d_in[10];
    const float* tm_mix_v = (const float*)d_in[11];
    const float* tm_mix_r = (const float*)d_in[12];
    const float* tm_decay = (const float*)d_in[13];
    const float* tm_first = (const float*)d_in[14];
    const float* Wk       = (const float*)d_in[15];
    const float* Wv       = (const float*)d_in[16];
    const float* Wr       = (const float*)d_in[17];
    const float* Wo       = (const float*)d_in[18];
    const float* cm_mix_k = (const float*)d_in[19];
    const float* cm_mix_r = (const float*)d_in[20];
    const float* Ck       = (const float*)d_in[21];
    const float* Cr       = (const float*)d_in[22];
    const float* Cv       = (const float*)d_in[23];

    float* out = (float*)d_out;
    const size_t OFS_XN1 = (size_t)MM * DD;
    const size_t OFS_AA  = OFS_XN1 + (size_t)BB * DD;
    const size_t OFS_BB  = OFS_AA  + (size_t)BB * DD;
    const size_t OFS_PP  = OFS_BB  + (size_t)BB * DD;
    const size_t OFS_XN2 = OFS_PP  + (size_t)BB * DD;

    float *xn, *mk, *mv, *mr, *kk, *vv, *rr, *rw, *x1, *xn2, *mck, *mcr, *kc, *rc;
    cudaGetSymbolAddress((void**)&xn,  g_xn);
    cudaGetSymbolAddress((void**)&mk,  g_mk);
    cudaGetSymbolAddress((void**)&mv,  g_mv);
    cudaGetSymbolAddress((void**)&mr,  g_mr);
    cudaGetSymbolAddress((void**)&kk,  g_k);
    cudaGetSymbolAddress((void**)&vv,  g_v);
    cudaGetSymbolAddress((void**)&rr,  g_r);
    cudaGetSymbolAddress((void**)&rw,  g_rw);
    cudaGetSymbolAddress((void**)&x1,  g_x1);
    cudaGetSymbolAddress((void**)&xn2, g_xn2);
    cudaGetSymbolAddress((void**)&mck, g_mck);
    cudaGetSymbolAddress((void**)&mcr, g_mcr);
    cudaGetSymbolAddress((void**)&kc,  g_kc);
    cudaGetSymbolAddress((void**)&rc,  g_rc);

    const int mixBlocks = (MM * D4 + 255) / 256;

    // 1) ln1(x) -> xn  (+ xn_last output)
    ln_kernel<<<MM, 256>>>(x, ln1_g, ln1_b, xn, out + OFS_XN1);

    // 2) token shift + mix for k/v/r
    mix_kernel<3><<<mixBlocks, 256>>>(xn, att_x, tm_mix_k, tm_mix_v, tm_mix_r, mk, mv, mr);

    // 3) K, V, R GEMMs (R fused sigmoid)
    dim3 gD(DD / 128, MM / 128);
    tgemm<0><<<gD, 256>>>(mk, Wk, kk, MM, DD, DD, nullptr, nullptr);
    tgemm<0><<<gD, 256>>>(mv, Wv, vv, MM, DD, DD, nullptr, nullptr);
    tgemm<1><<<gD, 256>>>(mr, Wr, rr, MM, DD, DD, nullptr, nullptr);

    // 4) WKV scan (fused r*wkv), state outputs — 64-thread blocks on 128 CTAs
    wkv_kernel<<<(BB * DD) / 64, 64>>>(kk, vv, rr, att_a, att_b, att_p,
                                       tm_decay, tm_first, rw,
                                       out + OFS_AA, out + OFS_BB, out + OFS_PP);

    // 5) x1 = x + (r*wkv) @ Wo
    tgemm<3><<<gD, 256>>>(rw, Wo, x1, MM, DD, DD, x, nullptr);

    // 6) ln2(x1) -> xn2 (+ xn2_last output)
    ln_kernel<<<MM, 256>>>(x1, ln2_g, ln2_b, xn2, out + OFS_XN2);

    // 7) channel-mix token shift
    mix_kernel<2><<<mixBlocks, 256>>>(xn2, ffn_x, cm_mix_k, cm_mix_r, nullptr, mck, mcr, nullptr);

    // 8) kc = relu(mck @ Ck)^2   [M=8192, N=4096, K=1024]
    dim3 gF(FF / 128, MM / 128);
    tgemm<2><<<gF, 256>>>(mck, Ck, kc, MM, FF, DD, nullptr, nullptr);

    // 9) rc = sigmoid(mcr @ Cr)
    tgemm<1><<<gD, 256>>>(mcr, Cr, rc, MM, DD, DD, nullptr, nullptr);

    // 10) out = x1 + rc * (kc @ Cv)   [M=8192, N=1024, K=4096]
    tgemm<4><<<gD, 256>>>(kc, Cv, out, MM, DD, FF, x1, rc);
}